// round 11
// baseline (speedup 1.0000x reference)
#include <cuda_runtime.h>
#include <cuda_fp16.h>
#include <cstdint>

#define NN_MAX 50000
#define NE_MAX 800000
#define FH 64
#define SCAN_BLK 256

// Scratch. deg|cnt|sync share one zeroed region (single memset node).
__device__ int    g_zr[2 * NN_MAX + 4];
#define G_DEG  ((float*)g_zr)
#define G_CNT  (g_zr + NN_MAX)
#define G_SYNC (g_zr + 2 * NN_MAX)     // [0]=cnt1 [1]=flag1 [2]=cnt2 [3]=flag2
__device__ int    g_start[NN_MAX];
__device__ int    g_cursor[NN_MAX];
__device__ int    g_bsum[SCAN_BLK];
__device__ int    g_boff[SCAN_BLK];
__device__ float2 g_es[NE_MAX];         // (row-bits, norm) bucketed by dst col
__device__ uint4  g_xh[NN_MAX * 8];     // x as fp16 (8 uint4 per node row)
__device__ uint4  g_tx1h[NN_MAX * 8];   // tx1 as fp16
__device__ uint4  g_p2h[NN_MAX * 8];    // p2 as fp16
#define B_STRH 200
__device__ __half g_Wch[128 * B_STRH];  // combined weights fp16, [n][k]

__device__ __forceinline__ float fast_sigmoid(float x) { return 1.f / (1.f + __expf(-x)); }
__device__ __forceinline__ float fast_tanh(float x) {
    float t = __expf(-2.f * fabsf(x));
    float r = (1.f - t) / (1.f + t);
    return copysignf(r, x);
}
__device__ __forceinline__ uint4 pack_h8(const float* a) {
    __half2 h0 = __floats2half2_rn(a[0], a[1]);
    __half2 h1 = __floats2half2_rn(a[2], a[3]);
    __half2 h2 = __floats2half2_rn(a[4], a[5]);
    __half2 h3 = __floats2half2_rn(a[6], a[7]);
    uint4 u;
    u.x = *(uint32_t*)&h0; u.y = *(uint32_t*)&h1;
    u.z = *(uint32_t*)&h2; u.w = *(uint32_t*)&h3;
    return u;
}

// ---------------------------------------------------------------------------
// Fused: deg/cnt histogram | combined-weight build (fp16) | x -> fp16 convert.
__global__ void k_prep(const int* __restrict__ row, const int* __restrict__ col,
                       const float* __restrict__ w, int ne, int n,
                       const float* __restrict__ Wxz, const float* __restrict__ Wxh,
                       const float* __restrict__ x) {
    int nbDeg = (ne + 255) >> 8;
    int bid = blockIdx.x;
    if (bid < nbDeg) {
        int e = bid * 256 + threadIdx.x;
        if (e < ne) {
            atomicAdd(G_DEG + row[e], w[e]);
            atomicAdd(G_CNT + col[e], 1);
        }
    } else if (bid < nbDeg + 96) {
        int t = (bid - nbDeg) * 256 + threadIdx.x;
        if (t < 192 * 128) {
            int k = t >> 7, j = t & 127;
            const float* W = (j < 64) ? Wxz : Wxh;
            int jj = j & 63;
            float v;
            if (k < 64)       v = W[k * 64 + jj] - W[2 * 4096 + k * 64 + jj];
            else if (k < 128) v = W[4096 + (k - 64) * 64 + jj];
            else              v = 2.f * W[2 * 4096 + (k - 128) * 64 + jj];
            g_Wch[j * B_STRH + k] = __float2half_rn(v);
        }
    } else {
        int t = (bid - nbDeg - 96) * 256 + threadIdx.x;
        if (t < n * 8) {
            float4 a = ((const float4*)x)[t * 2];
            float4 b = ((const float4*)x)[t * 2 + 1];
            float f[8] = {a.x, a.y, a.z, a.w, b.x, b.y, b.z, b.w};
            g_xh[t] = pack_h8(f);
        }
    }
}

// Single kernel: exclusive scan of cnt -> start/cursor, grid-sync, then scatter.
__global__ void k_scan_scatter(int n, int nblk,
                               const int* __restrict__ row, const int* __restrict__ col,
                               const float* __restrict__ w, int ne) {
    __shared__ int s[SCAN_BLK];
    __shared__ int sl;
    int t = threadIdx.x;
    int i = blockIdx.x * SCAN_BLK + t;
    int v = (i < n) ? G_CNT[i] : 0;
    s[t] = v; __syncthreads();
    #pragma unroll
    for (int o = 1; o < SCAN_BLK; o <<= 1) {
        int u = (t >= o) ? s[t - o] : 0;
        __syncthreads(); s[t] += u; __syncthreads();
    }
    int incl = s[t];
    if (t == SCAN_BLK - 1) g_bsum[blockIdx.x] = incl;
    __threadfence();
    __syncthreads();
    if (t == 0) sl = (atomicAdd(G_SYNC + 0, 1) == nblk - 1) ? 1 : 0;
    __syncthreads();
    if (sl) {
        int bv = (t < nblk) ? g_bsum[t] : 0;
        s[t] = bv; __syncthreads();
        #pragma unroll
        for (int o = 1; o < SCAN_BLK; o <<= 1) {
            int u = (t >= o) ? s[t - o] : 0;
            __syncthreads(); s[t] += u; __syncthreads();
        }
        g_boff[t] = s[t] - bv;
        __threadfence();
        __syncthreads();
        if (t == 0) atomicExch(G_SYNC + 1, 1);
    }
    if (t == 0) { while (atomicAdd(G_SYNC + 1, 0) == 0) {} }
    __syncthreads();
    if (i < n) {
        int st = g_boff[blockIdx.x] + incl - v;
        g_start[i] = st;
        g_cursor[i] = st;
    }

    // ---- grid sync 2: all cursors visible, then grid-stride scatter ----
    __threadfence();
    __syncthreads();
    if (t == 0) {
        if (atomicAdd(G_SYNC + 2, 1) == nblk - 1) atomicExch(G_SYNC + 3, 1);
        while (atomicAdd(G_SYNC + 3, 0) == 0) {}
    }
    __syncthreads();

    int stride = nblk * SCAN_BLK;
    for (int e = blockIdx.x * SCAN_BLK + t; e < ne; e += stride) {
        int r = row[e], c = col[e];
        float dr = G_DEG[r], dc = G_DEG[c];
        float ir = dr > 0.f ? rsqrtf(dr) : 0.f;
        float ic = dc > 0.f ? rsqrtf(dc) : 0.f;
        float nm = -ir * w[e] * ic;
        int pos = atomicAdd(g_cursor + c, 1);
        g_es[pos] = make_float2(__int_as_float(r), nm);
    }
}

// Gather prop (fp16 src -> fp16 dst): 8 threads/node, 16B loads, unroll-4.
#define ACC8(nm, u) do { \
    float2 f0 = __half22float2(*(__half2*)&(u).x); \
    float2 f1 = __half22float2(*(__half2*)&(u).y); \
    float2 f2 = __half22float2(*(__half2*)&(u).z); \
    float2 f3 = __half22float2(*(__half2*)&(u).w); \
    acc[0] = fmaf(nm, f0.x, acc[0]); acc[1] = fmaf(nm, f0.y, acc[1]); \
    acc[2] = fmaf(nm, f1.x, acc[2]); acc[3] = fmaf(nm, f1.y, acc[3]); \
    acc[4] = fmaf(nm, f2.x, acc[4]); acc[5] = fmaf(nm, f2.y, acc[5]); \
    acc[6] = fmaf(nm, f3.x, acc[6]); acc[7] = fmaf(nm, f3.y, acc[7]); } while (0)

__global__ void k_gatherh(const uint4* __restrict__ src, uint4* __restrict__ dst, int n) {
    int t = blockIdx.x * blockDim.x + threadIdx.x;
    int node = t >> 3, h = t & 7;
    if (node >= n) return;
    int beg = g_start[node], cnt = G_CNT[node];
    const float2* ep = g_es + beg;
    float acc[8];
    #pragma unroll
    for (int i = 0; i < 8; ++i) acc[i] = 0.f;
    int k = 0;
    for (; k + 4 <= cnt; k += 4) {
        float2 e0 = ep[k], e1 = ep[k + 1], e2 = ep[k + 2], e3 = ep[k + 3];
        uint4 u0 = src[(__float_as_int(e0.x) << 3) + h];
        uint4 u1 = src[(__float_as_int(e1.x) << 3) + h];
        uint4 u2 = src[(__float_as_int(e2.x) << 3) + h];
        uint4 u3 = src[(__float_as_int(e3.x) << 3) + h];
        ACC8(e0.y, u0); ACC8(e1.y, u1); ACC8(e2.y, u2); ACC8(e3.y, u3);
    }
    for (; k < cnt; ++k) {
        float2 e0 = ep[k];
        uint4 u0 = src[(__float_as_int(e0.x) << 3) + h];
        ACC8(e0.y, u0);
    }
    dst[(node << 3) + h] = pack_h8(acc);
}

// ---------------------------------------------------------------------------
// k_final: 128 nodes/block; D[128x128] = A[128x192]@B via mma.m16n8k16.f16.
#define A_STRH 200              // halves per A row (400B; word stride 100)
#define A_STRW 100
#define SM_BZ   0
#define SM_BH   256
#define SM_WLIN 512
#define SM_A    1024
#define SMEM_BYTES (SM_A + 128 * A_STRH * 2)   // 52224

__device__ __forceinline__ void mma16(float* c, const uint32_t* a, const uint32_t* b) {
    asm volatile("mma.sync.aligned.m16n8k16.row.col.f32.f16.f16.f32 "
                 "{%0,%1,%2,%3}, {%4,%5,%6,%7}, {%8,%9}, {%0,%1,%2,%3};"
                 : "+f"(c[0]), "+f"(c[1]), "+f"(c[2]), "+f"(c[3])
                 : "r"(a[0]), "r"(a[1]), "r"(a[2]), "r"(a[3]), "r"(b[0]), "r"(b[1]));
}

__global__ void __launch_bounds__(256, 2)
k_final(const float* __restrict__ bxz, const float* __restrict__ bhz,
        const float* __restrict__ bxh, const float* __restrict__ bhh,
        const float* __restrict__ Wlin, const float* __restrict__ blin,
        float* __restrict__ out, int n) {
    extern __shared__ __align__(16) char smem[];
    float* sBz = (float*)(smem + SM_BZ);
    float* sBh = (float*)(smem + SM_BH);
    float* sWl = (float*)(smem + SM_WLIN);
    char*  As  = smem + SM_A;
    const uint32_t* Au = (const uint32_t*)As;
    const uint32_t* Bg = (const uint32_t*)g_Wch;

    int tid = threadIdx.x, wid = tid >> 5, lane = tid & 31;
    int blk = blockIdx.x;

    // Stage A (uint4 copies): halves [0:64)=x, [64:128)=tx1, [128:192)=p2
    for (int idx = tid; idx < 128 * 24; idx += 256) {
        int m = idx / 24, seg = idx % 24;
        int g = blk * 128 + m;
        uint4 u = make_uint4(0u, 0u, 0u, 0u);
        if (g < n) {
            u = (seg < 8)  ? g_xh[g * 8 + seg]
              : (seg < 16) ? g_tx1h[g * 8 + (seg - 8)]
                           : g_p2h[g * 8 + (seg - 16)];
        }
        *(uint4*)(As + m * 400 + seg * 16) = u;
    }

    if (tid < 64) {
        sBz[tid] = bxz[tid] + bhz[tid];
        sBh[tid] = bxh[tid] + bhh[tid];
    }
    if (tid < 128) sWl[tid] = Wlin[tid];
    __syncthreads();

    int mw = wid >> 2, nw = wid & 3;
    int g8 = lane >> 2, t4 = lane & 3;
    int m0 = mw * 64, n0 = nw * 32;

    float acc[4][4][4];
    #pragma unroll
    for (int mt = 0; mt < 4; ++mt)
        #pragma unroll
        for (int nt = 0; nt < 4; ++nt)
            #pragma unroll
            for (int e = 0; e < 4; ++e) acc[mt][nt][e] = 0.f;

    uint32_t b[4][2];
    #pragma unroll
    for (int nt = 0; nt < 4; ++nt) {
        int cN = n0 + nt * 8 + g8;
        b[nt][0] = __ldg(Bg + cN * A_STRW + t4);
        b[nt][1] = __ldg(Bg + cN * A_STRW + 4 + t4);
    }

    #pragma unroll
    for (int ks = 0; ks < 12; ++ks) {
        int kw = ks * 8;
        uint32_t a[4][4];
        #pragma unroll
        for (int mt = 0; mt < 4; ++mt) {
            int r0 = m0 + mt * 16;
            a[mt][0] = Au[(r0 + g8)     * A_STRW + kw + t4];
            a[mt][1] = Au[(r0 + g8 + 8) * A_STRW + kw + t4];
            a[mt][2] = Au[(r0 + g8)     * A_STRW + kw + 4 + t4];
            a[mt][3] = Au[(r0 + g8 + 8) * A_STRW + kw + 4 + t4];
        }
        uint32_t bc[4][2];
        #pragma unroll
        for (int nt = 0; nt < 4; ++nt) { bc[nt][0] = b[nt][0]; bc[nt][1] = b[nt][1]; }
        if (ks < 11) {
            int kw1 = kw + 8;
            #pragma unroll
            for (int nt = 0; nt < 4; ++nt) {
                int cN = n0 + nt * 8 + g8;
                b[nt][0] = __ldg(Bg + cN * A_STRW + kw1 + t4);
                b[nt][1] = __ldg(Bg + cN * A_STRW + kw1 + 4 + t4);
            }
        }
        #pragma unroll
        for (int mt = 0; mt < 4; ++mt)
            #pragma unroll
            for (int nt = 0; nt < 4; ++nt)
                mma16(acc[mt][nt], a[mt], bc[nt]);
    }
    __syncthreads();

    __half* Yh = (__half*)As;   // reuse A region, fp16 Y [128][A_STRH]
    #pragma unroll
    for (int mt = 0; mt < 4; ++mt) {
        #pragma unroll
        for (int nt = 0; nt < 4; ++nt) {
            int r = m0 + mt * 16 + g8;
            int c = n0 + nt * 8 + 2 * t4;
            __half2 lo = __floats2half2_rn(acc[mt][nt][0], acc[mt][nt][1]);
            __half2 hi = __floats2half2_rn(acc[mt][nt][2], acc[mt][nt][3]);
            *(__half2*)(Yh + r * A_STRH + c)       = lo;
            *(__half2*)(Yh + (r + 8) * A_STRH + c) = hi;
        }
    }
    __syncthreads();

    for (int t = tid; t < 128 * 32; t += 256) {
        int i = t >> 5, j2 = (t & 31) * 2;
        float2 czv = __half22float2(*(__half2*)(Yh + i * A_STRH + j2));
        float2 chv = __half22float2(*(__half2*)(Yh + i * A_STRH + 64 + j2));
        float z0  = fast_sigmoid(czv.x + sBz[j2]);
        float z1  = fast_sigmoid(czv.y + sBz[j2 + 1]);
        float h0  = fast_tanh(chv.x + sBh[j2]);
        float h1  = fast_tanh(chv.y + sBh[j2 + 1]);
        float t0  = fast_tanh((1.f - z0) * h0);
        float t1  = fast_tanh((1.f - z1) * h1);
        *(__half2*)(Yh + i * A_STRH + j2) = __floats2half2_rn(t0, t1);
    }
    __syncthreads();

    {
        int i = tid >> 1, c = tid & 1;
        int g = blk * 128 + i;
        if (g < n) {
            float s = blin[c];
            #pragma unroll 8
            for (int jj = 0; jj < 64; ++jj)
                s = fmaf(__half2float(Yh[i * A_STRH + jj]), sWl[2 * jj + c], s);
            out[g * 2 + c] = fast_sigmoid(s);
        }
    }
}

// ---------------------------------------------------------------------------
extern "C" void kernel_launch(void* const* d_in, const int* in_sizes, int n_in,
                              void* d_out, int out_size) {
    const float* x    = (const float*)d_in[0];
    const int*   ei   = (const int*)d_in[1];
    const float* ew   = (const float*)d_in[2];
    const float* Wxz  = (const float*)d_in[3];
    const float* bxz  = (const float*)d_in[4];
    const float* bhz  = (const float*)d_in[6];
    const float* Wxh  = (const float*)d_in[11];
    const float* bxh  = (const float*)d_in[12];
    const float* bhh  = (const float*)d_in[14];
    const float* Wlin = (const float*)d_in[15];
    const float* blin = (const float*)d_in[16];
    float* out = (float*)d_out;

    int n  = in_sizes[0] / FH;
    int ne = in_sizes[2];
    const int* row = ei;
    const int* col = ei + ne;
    int nblk  = (n + SCAN_BLK - 1) / SCAN_BLK;
    int nbDeg = (ne + 255) >> 8;
    int nbX   = (n * 8 + 255) >> 8;

    cudaFuncSetAttribute(k_final, cudaFuncAttributeMaxDynamicSharedMemorySize, SMEM_BYTES);

    void* p_zr;  cudaGetSymbolAddress(&p_zr, g_zr);
    cudaMemsetAsync(p_zr, 0, (size_t)(2 * NN_MAX + 4) * sizeof(int), 0);

    uint4 *p_xh, *p_tx1h, *p_p2h;
    cudaGetSymbolAddress((void**)&p_xh, g_xh);
    cudaGetSymbolAddress((void**)&p_tx1h, g_tx1h);
    cudaGetSymbolAddress((void**)&p_p2h, g_p2h);

    k_prep<<<nbDeg + 96 + nbX, 256>>>(row, col, ew, ne, n, Wxz, Wxh, x);
    k_scan_scatter<<<nblk, SCAN_BLK>>>(n, nblk, row, col, ew, ne);
    k_gatherh<<<(n * 8 + 255) / 256, 256>>>(p_xh, p_tx1h, n);
    k_gatherh<<<(n * 8 + 255) / 256, 256>>>(p_tx1h, p_p2h, n);
    k_final<<<(n + 127) / 128, 256, SMEM_BYTES>>>(bxz, bhz, bxh, bhh, Wlin, blin, out, n);
}